// round 13
// baseline (speedup 1.0000x reference)
#include <cuda_runtime.h>
#include <cuda_bf16.h>

// FM layer: out[b,:] = 0.5 * ((sum v*e)^2 - sum (v*e)^2), batch_ids sorted.
//
// SINGLE fused kernel. Each CTA finds its segment bounds with ONE round of
// independent coalesced loads: batch_ids is uniform-random, so segment b
// starts near p0 = b*nnz/batch (max deviation ~4 sigma ~ 1800 < W=3072).
// The CTA counts elements < b and <= b inside window [p0-W, p0+W] -> exact
// lower bounds. A bracket check with widen-and-retry fallback guarantees
// correctness for any input. Unlike R7's binary search (5 DEPENDENT probe
// rounds, cost ~8us), this is one L2 round-trip of independent loads.
//
// Gather body = converged R2 configuration (38.0-38.9us, random-256B-row
// HBM ceiling ~4.3TB/s; verified across 5 structural variants).
//
// Inputs:
//   d_in[0] feature_embedding float32 [1e6, 64]
//   d_in[1] feature_vals      float32 [819200]
//   d_in[2] batch_ids         int32   [819200] sorted
//   d_in[3] feat_ids          int32   [819200]
//   d_in[4] batch_size        int32   [1]
// Output float32 [4096, 64]

#define EMBED  64
#define GROUPS 8              // 8 warps per CTA, group-strided over the segment
#define BLOCK  256
#define WIN    3072           // initial half-window for the bound estimate

__global__ __launch_bounds__(BLOCK, 8)
void fm_fused(const float* __restrict__ emb,
              const float* __restrict__ vals,
              const int*   __restrict__ bids,
              const int*   __restrict__ fids,
              float*       __restrict__ out,
              int nnz, int batch)
{
    const int b   = blockIdx.x;
    const int tid = threadIdx.x;
    const int t   = tid & 31;           // float2 lane: dims [2t, 2t+1]
    const int g   = tid >> 5;           // warp/group 0..7

    __shared__ int s_ok, s_c1, s_c2;

    // ---- one-round windowed bound search (independent coalesced loads) ----
    const long long p0 = ((long long)b * nnz) / batch;
    int lo, hi;
    long long W = WIN;
    while (true) {
        int lo_w = (int)((p0 - W < 0) ? 0 : p0 - W);
        long long hw = p0 + W;
        int hi_w = (hw > nnz) ? nnz : (int)hw;

        if (tid == 0) {
            bool okLo = (lo_w == 0)  || (__ldg(bids + lo_w - 1) < b);
            bool okHi = (hi_w == nnz) || (__ldg(bids + hi_w) > b);
            s_ok = okLo && okHi;
            s_c1 = 0; s_c2 = 0;
        }
        __syncthreads();
        if (s_ok) {
            int c1 = 0, c2 = 0;
            #pragma unroll 4
            for (int idx = lo_w + tid; idx < hi_w; idx += BLOCK) {
                int v = __ldg(bids + idx);
                c1 += (v <  b);
                c2 += (v <= b);
            }
            c1 = __reduce_add_sync(0xffffffffu, c1);
            c2 = __reduce_add_sync(0xffffffffu, c2);
            if (t == 0) { atomicAdd(&s_c1, c1); atomicAdd(&s_c2, c2); }
            __syncthreads();
            lo = lo_w + s_c1;
            hi = lo_w + s_c2;
            break;
        }
        __syncthreads();      // shared reuse safety before retry
        W <<= 2;              // widen (statistically never taken)
    }

    // ---- converged gather body (R2) ----
    const float2* __restrict__ emb2 = (const float2*)emb;

    float sx = 0.f, sy = 0.f, qx = 0.f, qy = 0.f;

    int i = lo + g;
    for (; i + 3 * GROUPS < hi; i += 4 * GROUPS) {
        int f0 = __ldg(fids + i);
        int f1 = __ldg(fids + i +     GROUPS);
        int f2 = __ldg(fids + i + 2 * GROUPS);
        int f3 = __ldg(fids + i + 3 * GROUPS);
        float v0 = __ldg(vals + i);
        float v1 = __ldg(vals + i +     GROUPS);
        float v2 = __ldg(vals + i + 2 * GROUPS);
        float v3 = __ldg(vals + i + 3 * GROUPS);
        float2 e0 = __ldg(emb2 + f0 * 32 + t);
        float2 e1 = __ldg(emb2 + f1 * 32 + t);
        float2 e2 = __ldg(emb2 + f2 * 32 + t);
        float2 e3 = __ldg(emb2 + f3 * 32 + t);

        float ax, ay;
        ax = v0 * e0.x; ay = v0 * e0.y; sx += ax; qx = fmaf(ax, ax, qx); sy += ay; qy = fmaf(ay, ay, qy);
        ax = v1 * e1.x; ay = v1 * e1.y; sx += ax; qx = fmaf(ax, ax, qx); sy += ay; qy = fmaf(ay, ay, qy);
        ax = v2 * e2.x; ay = v2 * e2.y; sx += ax; qx = fmaf(ax, ax, qx); sy += ay; qy = fmaf(ay, ay, qy);
        ax = v3 * e3.x; ay = v3 * e3.y; sx += ax; qx = fmaf(ax, ax, qx); sy += ay; qy = fmaf(ay, ay, qy);
    }
    for (; i < hi; i += GROUPS) {
        int   f = __ldg(fids + i);
        float v = __ldg(vals + i);
        float2 e = __ldg(emb2 + f * 32 + t);
        float ax = v * e.x, ay = v * e.y;
        sx += ax; qx = fmaf(ax, ax, qx);
        sy += ay; qy = fmaf(ay, ay, qy);
    }

    // ---- combine 8 groups through shared memory ----
    __shared__ float ssx[GROUPS][32], ssy[GROUPS][32];
    __shared__ float sqx[GROUPS][32], sqy[GROUPS][32];
    ssx[g][t] = sx; ssy[g][t] = sy;
    sqx[g][t] = qx; sqy[g][t] = qy;
    __syncthreads();

    if (g == 0) {
        float Sx = sx, Sy = sy, Qx = qx, Qy = qy;
        #pragma unroll
        for (int k = 1; k < GROUPS; k++) {
            Sx += ssx[k][t]; Sy += ssy[k][t];
            Qx += sqx[k][t]; Qy += sqy[k][t];
        }
        float2 o;
        o.x = 0.5f * (Sx * Sx - Qx);
        o.y = 0.5f * (Sy * Sy - Qy);
        ((float2*)out)[b * 32 + t] = o;
    }
}

extern "C" void kernel_launch(void* const* d_in, const int* in_sizes, int n_in,
                              void* d_out, int out_size)
{
    const float* emb  = (const float*)d_in[0];
    const float* vals = (const float*)d_in[1];
    const int*   bids = (const int*)d_in[2];
    const int*   fids = (const int*)d_in[3];
    float* out = (float*)d_out;

    int nnz   = in_sizes[1];
    int batch = out_size / EMBED;   // 4096

    fm_fused<<<batch, BLOCK>>>(emb, vals, bids, fids, out, nnz, batch);
}

// round 14
// speedup vs baseline: 1.0655x; 1.0655x over previous
#include <cuda_runtime.h>
#include <cuda_bf16.h>

// FM layer: out[b,:] = 0.5 * ((sum v*e)^2 - sum (v*e)^2), batch_ids sorted.
//
// SINGLE kernel, no duplicated scan work (fixes R7/R13 fusion failures):
//   Phase 1: CTA b scans ITS OWN 1/4096 slice of batch_ids (~200 elems,
//            1 per thread) and publishes CSR transitions to g_starts via
//            atomic stores (value = lo+1; 0 means "not yet written").
//            Total scan work == the standalone boundary kernel, but fused.
//   Phase 2: thread 0 spin-waits (nanosleep backoff) for its two entries.
//            Producers are CTAs within ~±10 of this CTA's index (boundary
//            deviation <= 4 sigma ~ 1800 = 9 slices), so in any resident
//            wave only the topmost handful of CTAs wait on future CTAs;
//            everyone else drains and frees slots -> guaranteed progress.
//   Phase 3: converged gather body (R2 config; HBM random-256B-row ceiling
//            ~4.3TB/s, verified across 5 structural variants).
//
// Inputs:
//   d_in[0] feature_embedding float32 [1e6, 64]
//   d_in[1] feature_vals      float32 [819200]
//   d_in[2] batch_ids         int32   [819200] sorted
//   d_in[3] feat_ids          int32   [819200]
//   d_in[4] batch_size        int32   [1]
// Output float32 [4096, 64]

#define EMBED  64
#define GROUPS 8              // 8 warps per CTA, group-strided over the segment
#define BLOCK  256

__device__ int g_starts[4097];   // stores (row_start + 1); 0 = unwritten

__global__ __launch_bounds__(BLOCK, 8)
void fm_fused(const float* __restrict__ emb,
              const float* __restrict__ vals,
              const int*   __restrict__ bids,
              const int*   __restrict__ fids,
              float*       __restrict__ out,
              int nnz, int batch)
{
    const int b   = blockIdx.x;
    const int tid = threadIdx.x;
    const int t   = tid & 31;           // float2 lane: dims [2t, 2t+1]
    const int g   = tid >> 5;           // warp/group 0..7

    // ---- Phase 1: scan own slice, publish transitions (exactly-once) ----
    {
        const int spt = (nnz + gridDim.x - 1) / (int)gridDim.x;   // 200
        const int s0  = b * spt;
        const int s1  = (s0 + spt < nnz) ? s0 + spt : nnz;
        for (int i = s0 + tid; i < s1; i += BLOCK) {
            int prev = (i == 0) ? -1 : __ldg(bids + i - 1);
            int cur  = __ldg(bids + i);
            for (int r = prev + 1; r <= cur; r++)
                atomicExch(&g_starts[r], i + 1);
            if (i == nnz - 1) {
                for (int r = cur + 1; r <= batch; r++)
                    atomicExch(&g_starts[r], nnz + 1);
            }
        }
        __threadfence();
    }

    // ---- Phase 2: acquire this CTA's bounds (spin only until producers land) ----
    __shared__ int s_lo, s_hi;
    if (tid == 0) {
        int v;
        while ((v = atomicAdd(&g_starts[b], 0)) == 0) __nanosleep(64);
        s_lo = v - 1;
        while ((v = atomicAdd(&g_starts[b + 1], 0)) == 0) __nanosleep(64);
        s_hi = v - 1;
    }
    __syncthreads();
    const int lo = s_lo;
    const int hi = s_hi;

    // ---- Phase 3: converged gather body ----
    const float2* __restrict__ emb2 = (const float2*)emb;

    float sx = 0.f, sy = 0.f, qx = 0.f, qy = 0.f;

    int i = lo + g;
    for (; i + 3 * GROUPS < hi; i += 4 * GROUPS) {
        int f0 = __ldg(fids + i);
        int f1 = __ldg(fids + i +     GROUPS);
        int f2 = __ldg(fids + i + 2 * GROUPS);
        int f3 = __ldg(fids + i + 3 * GROUPS);
        float v0 = __ldg(vals + i);
        float v1 = __ldg(vals + i +     GROUPS);
        float v2 = __ldg(vals + i + 2 * GROUPS);
        float v3 = __ldg(vals + i + 3 * GROUPS);
        float2 e0 = __ldg(emb2 + f0 * 32 + t);
        float2 e1 = __ldg(emb2 + f1 * 32 + t);
        float2 e2 = __ldg(emb2 + f2 * 32 + t);
        float2 e3 = __ldg(emb2 + f3 * 32 + t);

        float ax, ay;
        ax = v0 * e0.x; ay = v0 * e0.y; sx += ax; qx = fmaf(ax, ax, qx); sy += ay; qy = fmaf(ay, ay, qy);
        ax = v1 * e1.x; ay = v1 * e1.y; sx += ax; qx = fmaf(ax, ax, qx); sy += ay; qy = fmaf(ay, ay, qy);
        ax = v2 * e2.x; ay = v2 * e2.y; sx += ax; qx = fmaf(ax, ax, qx); sy += ay; qy = fmaf(ay, ay, qy);
        ax = v3 * e3.x; ay = v3 * e3.y; sx += ax; qx = fmaf(ax, ax, qx); sy += ay; qy = fmaf(ay, ay, qy);
    }
    for (; i < hi; i += GROUPS) {
        int   f = __ldg(fids + i);
        float v = __ldg(vals + i);
        float2 e = __ldg(emb2 + f * 32 + t);
        float ax = v * e.x, ay = v * e.y;
        sx += ax; qx = fmaf(ax, ax, qx);
        sy += ay; qy = fmaf(ay, ay, qy);
    }

    // ---- combine 8 groups through shared memory ----
    __shared__ float ssx[GROUPS][32], ssy[GROUPS][32];
    __shared__ float sqx[GROUPS][32], sqy[GROUPS][32];
    ssx[g][t] = sx; ssy[g][t] = sy;
    sqx[g][t] = qx; sqy[g][t] = qy;
    __syncthreads();

    if (g == 0) {
        float Sx = sx, Sy = sy, Qx = qx, Qy = qy;
        #pragma unroll
        for (int k = 1; k < GROUPS; k++) {
            Sx += ssx[k][t]; Sy += ssy[k][t];
            Qx += sqx[k][t]; Qy += sqy[k][t];
        }
        float2 o;
        o.x = 0.5f * (Sx * Sx - Qx);
        o.y = 0.5f * (Sy * Sy - Qy);
        ((float2*)out)[b * 32 + t] = o;
    }
}

extern "C" void kernel_launch(void* const* d_in, const int* in_sizes, int n_in,
                              void* d_out, int out_size)
{
    const float* emb  = (const float*)d_in[0];
    const float* vals = (const float*)d_in[1];
    const int*   bids = (const int*)d_in[2];
    const int*   fids = (const int*)d_in[3];
    float* out = (float*)d_out;

    int nnz   = in_sizes[1];
    int batch = out_size / EMBED;   // 4096

    fm_fused<<<batch, BLOCK>>>(emb, vals, bids, fids, out, nnz, batch);
}

// round 15
// speedup vs baseline: 1.1097x; 1.0414x over previous
#include <cuda_runtime.h>
#include <cuda_bf16.h>

// FM layer: out[b,:] = 0.5 * ((sum v*e)^2 - sum (v*e)^2), batch_ids sorted.
//
// FINAL configuration — empirical argmax over 14 rounds (best total 41.28us):
//   * boundary_kernel: sorted batch_ids -> CSR row starts, 1 elem/thread,
//     exactly-once transition writes, no atomics (~1.5us; every "smarter"
//     variant — EPT 4/16/32, fused binary search, fused windowed scan,
//     fused flag hand-off, PDL — measured worse or neutral).
//   * fm_main: 1 CTA per batch row, 8 groups x 32 threads (float2 lanes),
//     4-deep independent gather pipeline, 32 regs, 8 CTAs/SM (occ ~88%).
//     Body is pinned at the random-256B-row HBM ceiling (~4.3TB/s, ~55% of
//     spec; ~165MB moved vs ~154MB mandatory) across 7 structural variants.
//
// Inputs:
//   d_in[0] feature_embedding float32 [1e6, 64]
//   d_in[1] feature_vals      float32 [819200]
//   d_in[2] batch_ids         int32   [819200] sorted
//   d_in[3] feat_ids          int32   [819200]
//   d_in[4] batch_size        int32   [1]
// Output float32 [4096, 64]

#define EMBED  64
#define GROUPS 8              // 8 warps per CTA, group-strided over the segment
#define BLOCK  256

__device__ int g_starts[4097];

// Sorted batch_ids -> CSR row starts. Exactly-once, no atomics.
__global__ void boundary_kernel(const int* __restrict__ bids, int nnz, int batch)
{
    int i = blockIdx.x * blockDim.x + threadIdx.x;
    if (i > nnz) return;
    int prev = (i == 0)   ? -1    : __ldg(bids + i - 1);
    int cur  = (i == nnz) ? batch : __ldg(bids + i);
    for (int b = prev + 1; b <= cur; b++)
        g_starts[b] = i;
}

__global__ __launch_bounds__(BLOCK, 8)
void fm_main(const float* __restrict__ emb,
             const float* __restrict__ vals,
             const int*   __restrict__ fids,
             float*       __restrict__ out)
{
    const int b = blockIdx.x;
    const int t = threadIdx.x & 31;     // float2 lane: dims [2t, 2t+1]
    const int g = threadIdx.x >> 5;     // warp/group 0..7

    const int lo = g_starts[b];
    const int hi = g_starts[b + 1];

    const float2* __restrict__ emb2 = (const float2*)emb;

    float sx = 0.f, sy = 0.f, qx = 0.f, qy = 0.f;

    int i = lo + g;
    // 4-deep independent gather pipeline per thread
    for (; i + 3 * GROUPS < hi; i += 4 * GROUPS) {
        int f0 = __ldg(fids + i);
        int f1 = __ldg(fids + i +     GROUPS);
        int f2 = __ldg(fids + i + 2 * GROUPS);
        int f3 = __ldg(fids + i + 3 * GROUPS);
        float v0 = __ldg(vals + i);
        float v1 = __ldg(vals + i +     GROUPS);
        float v2 = __ldg(vals + i + 2 * GROUPS);
        float v3 = __ldg(vals + i + 3 * GROUPS);
        float2 e0 = __ldg(emb2 + f0 * 32 + t);
        float2 e1 = __ldg(emb2 + f1 * 32 + t);
        float2 e2 = __ldg(emb2 + f2 * 32 + t);
        float2 e3 = __ldg(emb2 + f3 * 32 + t);

        float ax, ay;
        ax = v0 * e0.x; ay = v0 * e0.y; sx += ax; qx = fmaf(ax, ax, qx); sy += ay; qy = fmaf(ay, ay, qy);
        ax = v1 * e1.x; ay = v1 * e1.y; sx += ax; qx = fmaf(ax, ax, qx); sy += ay; qy = fmaf(ay, ay, qy);
        ax = v2 * e2.x; ay = v2 * e2.y; sx += ax; qx = fmaf(ax, ax, qx); sy += ay; qy = fmaf(ay, ay, qy);
        ax = v3 * e3.x; ay = v3 * e3.y; sx += ax; qx = fmaf(ax, ax, qx); sy += ay; qy = fmaf(ay, ay, qy);
    }
    for (; i < hi; i += GROUPS) {
        int   f = __ldg(fids + i);
        float v = __ldg(vals + i);
        float2 e = __ldg(emb2 + f * 32 + t);
        float ax = v * e.x, ay = v * e.y;
        sx += ax; qx = fmaf(ax, ax, qx);
        sy += ay; qy = fmaf(ay, ay, qy);
    }

    // combine 8 groups through shared memory
    __shared__ float ssx[GROUPS][32], ssy[GROUPS][32];
    __shared__ float sqx[GROUPS][32], sqy[GROUPS][32];
    ssx[g][t] = sx; ssy[g][t] = sy;
    sqx[g][t] = qx; sqy[g][t] = qy;
    __syncthreads();

    if (g == 0) {
        float Sx = sx, Sy = sy, Qx = qx, Qy = qy;
        #pragma unroll
        for (int k = 1; k < GROUPS; k++) {
            Sx += ssx[k][t]; Sy += ssy[k][t];
            Qx += sqx[k][t]; Qy += sqy[k][t];
        }
        float2 o;
        o.x = 0.5f * (Sx * Sx - Qx);
        o.y = 0.5f * (Sy * Sy - Qy);
        ((float2*)out)[b * 32 + t] = o;
    }
}

extern "C" void kernel_launch(void* const* d_in, const int* in_sizes, int n_in,
                              void* d_out, int out_size)
{
    const float* emb  = (const float*)d_in[0];
    const float* vals = (const float*)d_in[1];
    const int*   bids = (const int*)d_in[2];
    const int*   fids = (const int*)d_in[3];
    float* out = (float*)d_out;

    int nnz   = in_sizes[1];
    int batch = out_size / EMBED;   // 4096

    int bblocks = (nnz + 1 + 255) / 256;
    boundary_kernel<<<bblocks, 256>>>(bids, nnz, batch);
    fm_main<<<batch, BLOCK>>>(emb, vals, fids, out);
}